// round 12
// baseline (speedup 1.0000x reference)
#include <cuda_runtime.h>
#include <math.h>

#define BB 2
#define NN 4096
#define KK 30

#define SZ_POS (BB*NN*KK*16)
#define SZ_AD  (BB*NN*3)
#define SZ_OF  (BB*NN*KK*3)
#define SZ_GS  (BB*NN*KK*15)
#define SZ_DN  (BB*NN*KK)

#define OFF_POS 0
#define OFF_AD  (OFF_POS + SZ_POS)
#define OFF_OF  (OFF_AD  + SZ_AD)
#define OFF_GS  (OFF_OF  + SZ_OF)
#define OFF_DN  (OFF_GS  + SZ_GS)
#define OFF_EI  (OFF_DN  + SZ_DN)

typedef unsigned long long u64;
typedef unsigned int       u32;

// ---- grid ----
#define GDIM  32
#define GC    (GDIM*GDIM*GDIM)
#define GH    2.0f
#define GOFF  32.0f
#define CAPQ  512

static __device__ int    g_cnt[BB*GC];
static __device__ int    g_start[BB*GC + 1];
static __device__ int    g_cursor[BB*GC];
static __device__ float4 g_spts[BB*NN];
static __device__ int    g_bsum[64];

__device__ __forceinline__ int cellc(float v){
    int c = (int)floorf((v + GOFF) * 0.5f);
    return min(GDIM-1, max(0, c));
}

// ---- exact-rounding helpers ----
__device__ __forceinline__ float fadd_(float a, float b){ return __fadd_rn(a,b); }
__device__ __forceinline__ float fsub_(float a, float b){ return __fsub_rn(a,b); }
__device__ __forceinline__ float fmul_(float a, float b){ return __fmul_rn(a,b); }
__device__ __forceinline__ float dot3_(float ax,float ay,float az,
                                       float bx,float by,float bz){
    return fadd_(fadd_(fmul_(ax,bx), fmul_(ay,by)), fmul_(az,bz));
}
__device__ __forceinline__ void norm3_(float &x, float &y, float &z){
    float n = __fsqrt_rn(dot3_(x,y,z,x,y,z));
    n = fmaxf(n, 1e-12f);
    x = __fdiv_rn(x,n); y = __fdiv_rn(y,n); z = __fdiv_rn(z,n);
}
__device__ __forceinline__ void cross3_(float ax,float ay,float az,
                                        float bx,float by,float bz,
                                        float &cx,float &cy,float &cz){
    cx = fsub_(fmul_(ay,bz), fmul_(az,by));
    cy = fsub_(fmul_(az,bx), fmul_(ax,bz));
    cz = fsub_(fmul_(ax,by), fmul_(ay,bx));
}
__device__ __forceinline__ float d2_exact(float xi,float yi,float zi,
                                          float xj,float yj,float zj){
    float dx = fsub_(xj,xi), dy = fsub_(yj,yi), dz = fsub_(zj,zi);
    return fadd_(fadd_(fmul_(dx,dx), fmul_(dy,dy)), fmul_(dz,dz));
}

// ---- FP32 Cody-Waite 2pi reduction ----
#define INV_2PI  0.15915494309189535f
#define PI2_C1   6.2831855f
#define PI2_C2  -1.7484555e-07f
#define PI2_C3  -5.4469782e-15f
__device__ __forceinline__ float red2pi_(float ang){
    float k = rintf(ang * INV_2PI);
    float r = fmaf(-k, PI2_C1, ang);
    r = fmaf(-k, PI2_C2, r);
    r = fmaf(-k, PI2_C3, r);
    return r;
}

// ---- per-node orientation matrix + AD ----
__device__ void node_work(const float* __restrict__ X, float* __restrict__ outAD,
                          int id, float* __restrict__ sOmRow){
    int b = id / NN, n = id % NN;

    float O0=0,O1=0,O2=0,O3v=0,O4=0,O5=0,O6=0,O7=0,O8=0;
    float a0=0,a1=0,a2=0;

    if (n >= 1 && n <= NN-3){
        const float* Xb = X + b*NN*3;
        float p0x=Xb[(n-1)*3+0], p0y=Xb[(n-1)*3+1], p0z=Xb[(n-1)*3+2];
        float p1x=Xb[(n  )*3+0], p1y=Xb[(n  )*3+1], p1z=Xb[(n  )*3+2];
        float p2x=Xb[(n+1)*3+0], p2y=Xb[(n+1)*3+1], p2z=Xb[(n+1)*3+2];
        float p3x=Xb[(n+2)*3+0], p3y=Xb[(n+2)*3+1], p3z=Xb[(n+2)*3+2];

        float u2x=fsub_(p1x,p0x), u2y=fsub_(p1y,p0y), u2z=fsub_(p1z,p0z); norm3_(u2x,u2y,u2z);
        float u1x=fsub_(p2x,p1x), u1y=fsub_(p2y,p1y), u1z=fsub_(p2z,p1z); norm3_(u1x,u1y,u1z);
        float u0x=fsub_(p3x,p2x), u0y=fsub_(p3y,p2y), u0z=fsub_(p3z,p2z); norm3_(u0x,u0y,u0z);

        float n2x,n2y,n2z; cross3_(u2x,u2y,u2z,u1x,u1y,u1z,n2x,n2y,n2z); norm3_(n2x,n2y,n2z);
        float n1x,n1y,n1z; cross3_(u1x,u1y,u1z,u0x,u0y,u0z,n1x,n1y,n1z); norm3_(n1x,n1y,n1z);

        const float lo = (float)(-1.0 + 1e-6);
        const float hi = (float)( 1.0 - 1e-6);
        float cosA = fminf(fmaxf(-dot3_(u1x,u1y,u1z,u0x,u0y,u0z), lo), hi);
        float A = acosf(cosA);
        float cosD = fminf(fmaxf(dot3_(n2x,n2y,n2z,n1x,n1y,n1z), lo), hi);
        float s = dot3_(u2x,u2y,u2z,n1x,n1y,n1z);
        float sg = (s > 0.0f) ? 1.0f : ((s < 0.0f) ? -1.0f : 0.0f);
        float Dang = fmul_(sg, acosf(cosD));

        float sA = sinf(A);
        a0 = cosf(A);
        a1 = fmul_(sA, cosf(Dang));
        a2 = fmul_(sA, sinf(Dang));

        float o1x=fsub_(u2x,u1x), o1y=fsub_(u2y,u1y), o1z=fsub_(u2z,u1z); norm3_(o1x,o1y,o1z);
        float cx,cy,cz; cross3_(o1x,o1y,o1z,n2x,n2y,n2z,cx,cy,cz);
        O0=o1x; O1=o1y; O2=o1z; O3v=n2x; O4=n2y; O5=n2z; O6=cx; O7=cy; O8=cz;
    }
    sOmRow[0]=O0; sOmRow[1]=O1; sOmRow[2]=O2; sOmRow[3]=O3v; sOmRow[4]=O4;
    sOmRow[5]=O5; sOmRow[6]=O6; sOmRow[7]=O7; sOmRow[8]=O8;
    outAD[id*3+0]=a0; outAD[id*3+1]=a1; outAD[id*3+2]=a2;
}

// ============================================================================
// Grid build kernels
// ============================================================================
__global__ void zero_kernel(){
    int id = blockIdx.x*blockDim.x + threadIdx.x;
    if (id < BB*GC) g_cnt[id] = 0;
}
__global__ void count_kernel(const float* __restrict__ X){
    int id = blockIdx.x*blockDim.x + threadIdx.x;
    if (id >= BB*NN) return;
    int b = id / NN;
    int cx = cellc(X[id*3+0]), cy = cellc(X[id*3+1]), cz = cellc(X[id*3+2]);
    atomicAdd(&g_cnt[b*GC + (cz*GDIM + cy)*GDIM + cx], 1);
}
__global__ void scanA_kernel(){
    __shared__ int sm[1024];
    int t = threadIdx.x;
    int gid = blockIdx.x*1024 + t;
    int v = g_cnt[gid];
    sm[t] = v; __syncthreads();
    for (int off = 512; off; off >>= 1){
        if (t < off) sm[t] += sm[t+off];
        __syncthreads();
    }
    if (t == 0) g_bsum[blockIdx.x] = sm[0];
}
__global__ void scanB_kernel(){
    if (threadIdx.x == 0){
        int run = 0;
        for (int i = 0; i < 64; i++){ int v = g_bsum[i]; g_bsum[i] = run; run += v; }
    }
}
__global__ void scanC_kernel(){
    __shared__ int sm[1024];
    int t = threadIdx.x;
    int gid = blockIdx.x*1024 + t;
    int v = g_cnt[gid];
    sm[t] = v; __syncthreads();
    for (int off = 1; off < 1024; off <<= 1){
        int x = (t >= off) ? sm[t-off] : 0;
        __syncthreads();
        sm[t] += x;
        __syncthreads();
    }
    int start = g_bsum[blockIdx.x] + sm[t] - v;   // exclusive
    g_start[gid] = start;
    g_cursor[gid] = start;
    if (gid == BB*GC - 1) g_start[BB*GC] = start + v;
}
__global__ void scatter_kernel(const float* __restrict__ X){
    int id = blockIdx.x*blockDim.x + threadIdx.x;
    if (id >= BB*NN) return;
    int b = id / NN, n = id % NN;
    float x = X[id*3+0], y = X[id*3+1], z = X[id*3+2];
    int cell = b*GC + (cellc(z)*GDIM + cellc(y))*GDIM + cellc(x);
    int pos = atomicAdd(&g_cursor[cell], 1);
    g_spts[pos] = make_float4(x, y, z, __int_as_float(n));
}

// ============================================================================
// Fused query kernel: grid-based exact top-30 kNN + node + edge features.
// Block = 8 rows, warp w = row r0+w.
// ============================================================================
#define TPB 256
#define RB  8

__global__ __launch_bounds__(TPB) void fused_kernel(
    const float* __restrict__ X, float* __restrict__ out)
{
    __shared__ u64   cand[RB][CAPQ];   // 32KB
    __shared__ float stD[RB][KK];
    __shared__ int   stI[RB][KK];
    __shared__ float sOm[RB][9];
    __shared__ float sfreq[8];
    __shared__ float smu[15];

    float* outP  = out + OFF_POS;
    float* outAD = out + OFF_AD;
    float* outO  = out + OFF_OF;
    float* outG  = out + OFF_GS;
    float* outD  = out + OFF_DN;
    float* outE  = out + OFF_EI;

    const int t = threadIdx.x, w = t >> 5, lane = t & 31;
    const int blk = blockIdx.x;
    const int b   = blk / (NN/RB);
    const int r0  = (blk % (NN/RB))*RB;
    const int bNN = b*NN;
    const float* Xb = X + b*NN*3;

    if (t < RB) node_work(X, outAD, bNN + r0 + t, sOm[t]);
    if (t >= 32 && t < 64){
        int u = t - 32;
        if (u < 8){
            float argf = __fmul_rn((float)(2*u), -0.5756462732485115f);
            sfreq[u] = (float)exp((double)argf);
        }
        if (u < 15) smu[u] = (float)((double)u * (20.0/14.0));
    }

    // ------------------ kNN query (one warp = one row) ------------------
    {
        const int row = r0 + w;
        const float xi = Xb[row*3+0], yi = Xb[row*3+1], zi = Xb[row*3+2];
        const int cx = cellc(xi), cy = cellc(yi), cz = cellc(zi);
        const int cbase = b*GC;
        u64* cw = cand[w];
        const u32 FULL = 0xffffffffu;

        // ---- phase A/B: gather whole shells until c >= KK ----
        int c = 0;
        int rho = 0;
        for (;; rho++){
            int side = 2*rho + 1;
            int tot = side*side*side;
            for (int q0 = 0; q0 < tot; q0 += 32){
                int q = q0 + lane;
                int s = 0, e = 0;
                if (q < tot){
                    int qz = q/(side*side); int rem = q - qz*(side*side);
                    int qy = rem/side;      int qx = rem - qy*side;
                    int dx = qx-rho, dy = qy-rho, dz = qz-rho;
                    int am = max(abs(dx), max(abs(dy), abs(dz)));
                    int ccx = cx+dx, ccy = cy+dy, ccz = cz+dz;
                    if (am == rho &&
                        ccx >= 0 && ccx < GDIM &&
                        ccy >= 0 && ccy < GDIM &&
                        ccz >= 0 && ccz < GDIM){
                        int cell = cbase + (ccz*GDIM + ccy)*GDIM + ccx;
                        s = g_start[cell]; e = g_start[cell+1];
                    }
                }
                int n_l = e - s;
                int inc = n_l;
                #pragma unroll
                for (int off = 1; off < 32; off <<= 1){
                    int v = __shfl_up_sync(FULL, inc, off);
                    if (lane >= off) inc += v;
                }
                int base = c + inc - n_l;
                for (int p = 0; p < n_l; p++){
                    float4 pt = g_spts[s + p];
                    float d2 = d2_exact(xi,yi,zi, pt.x,pt.y,pt.z);
                    int pos = base + p;
                    if (pos < CAPQ)
                        cw[pos] = ((u64)__float_as_uint(d2) << 32)
                                | (u32)__float_as_int(pt.w);
                }
                c += __shfl_sync(FULL, inc, 31);
            }
            if (c >= KK || rho >= GDIM) break;
        }
        int rho0 = rho;
        int c0 = min(c, CAPQ);

        // ---- phase C: certified d2 upper bound (binary search, 64 edges) ----
        float R = 1.75f * (float)(rho0 + 1) * GH;   // >= sqrt(3)*(rho0+1)*h
        float R2 = R * R;
        float dreg[16];
        int nreg = (c0 + 31) >> 5;
        #pragma unroll
        for (int q = 0; q < 16; q++){
            int idx = q*32 + lane;
            dreg[q] = (q < nreg && idx < c0)
                      ? __uint_as_float((u32)(cw[idx] >> 32)) : 1e30f;
        }
        int lo = 1, hi = 64;
        while (lo < hi){
            int mid = (lo + hi) >> 1;
            float edge = R2 * ((float)mid * 0.015625f);
            int cnt = 0;
            #pragma unroll
            for (int q = 0; q < 16; q++) cnt += (dreg[q] <= edge) ? 1 : 0;
            #pragma unroll
            for (int off = 16; off; off >>= 1)
                cnt += __shfl_xor_sync(FULL, cnt, off);
            if (cnt >= KK) hi = mid; else lo = mid + 1;
        }
        float d2ub = R2 * ((float)hi * 0.015625f) * 1.03125f;   // inflate

        // ---- phase D: remaining shells with min-dist <= bound, filtered ----
        for (int rho2 = rho0 + 1; rho2 <= GDIM; rho2++){
            float md = (float)(rho2 - 1) * GH;
            if (md*md > d2ub) break;
            int side = 2*rho2 + 1;
            int tot = side*side*side;
            for (int q0 = 0; q0 < tot; q0 += 32){
                int q = q0 + lane;
                int s = 0, e = 0;
                if (q < tot){
                    int qz = q/(side*side); int rem = q - qz*(side*side);
                    int qy = rem/side;      int qx = rem - qy*side;
                    int dx = qx-rho2, dy = qy-rho2, dz = qz-rho2;
                    int am = max(abs(dx), max(abs(dy), abs(dz)));
                    int ccx = cx+dx, ccy = cy+dy, ccz = cz+dz;
                    if (am == rho2 &&
                        ccx >= 0 && ccx < GDIM &&
                        ccy >= 0 && ccy < GDIM &&
                        ccz >= 0 && ccz < GDIM){
                        int cell = cbase + (ccz*GDIM + ccy)*GDIM + ccx;
                        s = g_start[cell]; e = g_start[cell+1];
                    }
                }
                e = min(e, s + 32);          // mask width guard (P(overflow)~0)
                u32 kmask = 0; int kcnt = 0;
                for (int p = s; p < e; p++){
                    float4 pt = g_spts[p];
                    float d2 = d2_exact(xi,yi,zi, pt.x,pt.y,pt.z);
                    if (d2 <= d2ub){ kmask |= 1u << (p - s); kcnt++; }
                }
                int inc = kcnt;
                #pragma unroll
                for (int off = 1; off < 32; off <<= 1){
                    int v = __shfl_up_sync(FULL, inc, off);
                    if (lane >= off) inc += v;
                }
                int base = c + inc - kcnt;
                int o = 0;
                for (int p = s; p < e; p++){
                    if ((kmask >> (p - s)) & 1u){
                        float4 pt = g_spts[p];
                        float d2 = d2_exact(xi,yi,zi, pt.x,pt.y,pt.z);
                        int pos = base + o;
                        if (pos < CAPQ)
                            cw[pos] = ((u64)__float_as_uint(d2) << 32)
                                    | (u32)__float_as_int(pt.w);
                        o++;
                    }
                }
                c += __shfl_sync(FULL, inc, 31);
            }
        }
        c = min(c, CAPQ);
        __syncwarp();

        // ---- exact (D, j) keys ----
        for (int idx = lane; idx < c; idx += 32){
            u64 kk = cw[idx];
            float d2 = __uint_as_float((u32)(kk >> 32));
            float D  = __fsqrt_rn(fadd_(d2, 1e-6f));
            cw[idx] = ((u64)__float_as_uint(D) << 32) | (kk & 0xFFFFFFFFull);
        }
        __syncwarp();

        // ---- rank selection ----
        const int base_o = (bNN + row)*KK;
        for (int idx = lane; idx < c; idx += 32){
            u64 k = cw[idx];
            int rank = 0;
            for (int cc2 = 0; cc2 < c; cc2++)
                rank += (cw[cc2] < k) ? 1 : 0;
            if (rank < KK){
                u32 jj = (u32)(k & 0xFFFFFFFFull);
                float D = __uint_as_float((u32)(k >> 32));
                outD[base_o + rank] = D;
                outE[base_o + rank] = (float)jj;
                stD[w][rank] = D;
                stI[w][rank] = (int)jj;
            }
        }
    }
    __syncthreads();

    // ---- edge phase A: positional encodings (8 x 30 x 16, coalesced) ----
    for (int id = t; id < RB*KK*16; id += TPB){
        int r = id / (KK*16);
        int q = id - r*(KK*16);
        int k = q >> 4, m = q & 15;
        int i = r0 + r;
        int j = stI[r][k];
        float d = fsub_((float)j, (float)i);
        float ang = fmul_(d, sfreq[m & 7]);
        float rr = red2pi_(ang);
        outP[(size_t)(bNN + i)*(KK*16) + q] = (m < 8) ? __cosf(rr) : __sinf(rr);
    }

    // ---- edge phase B: gaussian smearing (8 x 30 x 15, coalesced) ----
    for (int id = t; id < RB*KK*15; id += TPB){
        int r = id / (KK*15);
        int q = id - r*(KK*15);
        int k = q / 15, m = q - k*15;
        float D  = stD[r][k];
        float tt = fsub_(D, smu[m]) * 0.74999998f;
        outG[(size_t)(bNN + r0 + r)*(KK*15) + q] = __expf(-tt*tt);
    }

    // ---- edge phase C: dU via rsqrt normalize (8 x 30 edges) ----
    if (t < RB*KK){
        int r = t / KK, k = t - r*KK;
        int i = r0 + r;
        int j = stI[r][k];
        float dx = fsub_(Xb[j*3+0], Xb[i*3+0]);
        float dy = fsub_(Xb[j*3+1], Xb[i*3+1]);
        float dz = fsub_(Xb[j*3+2], Xb[i*3+2]);
        const float* Om = sOm[r];
        float v0 = dot3_(Om[0],Om[1],Om[2], dx,dy,dz);
        float v1 = dot3_(Om[3],Om[4],Om[5], dx,dy,dz);
        float v2 = dot3_(Om[6],Om[7],Om[8], dx,dy,dz);
        float s  = dot3_(v0,v1,v2,v0,v1,v2);
        float rn = rsqrtf(fmaxf(s, 1e-24f));
        size_t o = (size_t)((bNN + i)*KK + k)*3;
        outO[o+0] = v0*rn;
        outO[o+1] = v1*rn;
        outO[o+2] = v2*rn;
    }
}

// ============================================================================
extern "C" void kernel_launch(void* const* d_in, const int* in_sizes, int n_in,
                              void* d_out, int out_size)
{
    const float* X = (const float*)d_in[0];
    float* out = (float*)d_out;

    zero_kernel   <<<(BB*GC + 255)/256, 256>>>();
    count_kernel  <<<(BB*NN + 255)/256, 256>>>(X);
    scanA_kernel  <<<64, 1024>>>();
    scanB_kernel  <<<1, 64>>>();
    scanC_kernel  <<<64, 1024>>>();
    scatter_kernel<<<(BB*NN + 255)/256, 256>>>(X);
    fused_kernel  <<<BB*NN/RB, TPB>>>(X, out);
}

// round 13
// speedup vs baseline: 11.2234x; 11.2234x over previous
#include <cuda_runtime.h>
#include <math.h>

#define BB 2
#define NN 4096
#define KK 30

#define SZ_POS (BB*NN*KK*16)
#define SZ_AD  (BB*NN*3)
#define SZ_OF  (BB*NN*KK*3)
#define SZ_GS  (BB*NN*KK*15)
#define SZ_DN  (BB*NN*KK)

#define OFF_POS 0
#define OFF_AD  (OFF_POS + SZ_POS)
#define OFF_OF  (OFF_AD  + SZ_AD)
#define OFF_GS  (OFF_OF  + SZ_OF)
#define OFF_DN  (OFF_GS  + SZ_GS)
#define OFF_EI  (OFF_DN  + SZ_DN)

typedef unsigned long long u64;
typedef unsigned int       u32;

// ---- scratch ----
static __device__ float4 g_pts4[BB*NN];   // (x, y, z, |p|^2)

// ---- packed f32x2 helpers (sm_103a FFMA2 path, PTX-only) ----
__device__ __forceinline__ u64 pack2(float lo, float hi){
    u64 d; asm("mov.b64 %0, {%1, %2};" : "=l"(d) : "f"(lo), "f"(hi)); return d;
}
__device__ __forceinline__ u64 fma2(u64 a, u64 b, u64 c){
    u64 d; asm("fma.rn.f32x2 %0, %1, %2, %3;" : "=l"(d) : "l"(a), "l"(b), "l"(c)); return d;
}
__device__ __forceinline__ u64 mul2(u64 a, u64 b){
    u64 d; asm("mul.rn.f32x2 %0, %1, %2;" : "=l"(d) : "l"(a), "l"(b)); return d;
}
__device__ __forceinline__ u64 add2(u64 a, u64 b){
    u64 d; asm("add.rn.f32x2 %0, %1, %2;" : "=l"(d) : "l"(a), "l"(b)); return d;
}

// ---- exact-rounding helpers (OUTPUT values / selection keys) ----
__device__ __forceinline__ float fadd_(float a, float b){ return __fadd_rn(a,b); }
__device__ __forceinline__ float fsub_(float a, float b){ return __fsub_rn(a,b); }
__device__ __forceinline__ float fmul_(float a, float b){ return __fmul_rn(a,b); }
__device__ __forceinline__ float dot3_(float ax,float ay,float az,
                                       float bx,float by,float bz){
    return fadd_(fadd_(fmul_(ax,bx), fmul_(ay,by)), fmul_(az,bz));
}
__device__ __forceinline__ void norm3_(float &x, float &y, float &z){
    float n = __fsqrt_rn(dot3_(x,y,z,x,y,z));
    n = fmaxf(n, 1e-12f);
    x = __fdiv_rn(x,n); y = __fdiv_rn(y,n); z = __fdiv_rn(z,n);
}
__device__ __forceinline__ void cross3_(float ax,float ay,float az,
                                        float bx,float by,float bz,
                                        float &cx,float &cy,float &cz){
    cx = fsub_(fmul_(ay,bz), fmul_(az,by));
    cy = fsub_(fmul_(az,bx), fmul_(ax,bz));
    cz = fsub_(fmul_(ax,by), fmul_(ay,bx));
}
__device__ __forceinline__ float d2_exact(float xi,float yi,float zi,
                                          float xj,float yj,float zj){
    float dx = fsub_(xj,xi), dy = fsub_(yj,yi), dz = fsub_(zj,zi);
    return fadd_(fadd_(fmul_(dx,dx), fmul_(dy,dy)), fmul_(dz,dz));
}

// ---- FP32 Cody-Waite 2pi reduction ----
#define INV_2PI  0.15915494309189535f
#define PI2_C1   6.2831855f
#define PI2_C2  -1.7484555e-07f
#define PI2_C3  -5.4469782e-15f
__device__ __forceinline__ float red2pi_(float ang){
    float k = rintf(ang * INV_2PI);
    float r = fmaf(-k, PI2_C1, ang);
    r = fmaf(-k, PI2_C2, r);
    r = fmaf(-k, PI2_C3, r);
    return r;
}

// ---- per-node orientation matrix + AD ----
__device__ void node_work(const float* __restrict__ X, float* __restrict__ outAD,
                          int id, float* __restrict__ sOmRow){
    int b = id / NN, n = id % NN;

    float O0=0,O1=0,O2=0,O3v=0,O4=0,O5=0,O6=0,O7=0,O8=0;
    float a0=0,a1=0,a2=0;

    if (n >= 1 && n <= NN-3){
        const float* Xb = X + b*NN*3;
        float p0x=Xb[(n-1)*3+0], p0y=Xb[(n-1)*3+1], p0z=Xb[(n-1)*3+2];
        float p1x=Xb[(n  )*3+0], p1y=Xb[(n  )*3+1], p1z=Xb[(n  )*3+2];
        float p2x=Xb[(n+1)*3+0], p2y=Xb[(n+1)*3+1], p2z=Xb[(n+1)*3+2];
        float p3x=Xb[(n+2)*3+0], p3y=Xb[(n+2)*3+1], p3z=Xb[(n+2)*3+2];

        float u2x=fsub_(p1x,p0x), u2y=fsub_(p1y,p0y), u2z=fsub_(p1z,p0z); norm3_(u2x,u2y,u2z);
        float u1x=fsub_(p2x,p1x), u1y=fsub_(p2y,p1y), u1z=fsub_(p2z,p1z); norm3_(u1x,u1y,u1z);
        float u0x=fsub_(p3x,p2x), u0y=fsub_(p3y,p2y), u0z=fsub_(p3z,p2z); norm3_(u0x,u0y,u0z);

        float n2x,n2y,n2z; cross3_(u2x,u2y,u2z,u1x,u1y,u1z,n2x,n2y,n2z); norm3_(n2x,n2y,n2z);
        float n1x,n1y,n1z; cross3_(u1x,u1y,u1z,u0x,u0y,u0z,n1x,n1y,n1z); norm3_(n1x,n1y,n1z);

        const float lo = (float)(-1.0 + 1e-6);
        const float hi = (float)( 1.0 - 1e-6);
        float cosA = fminf(fmaxf(-dot3_(u1x,u1y,u1z,u0x,u0y,u0z), lo), hi);
        float A = acosf(cosA);
        float cosD = fminf(fmaxf(dot3_(n2x,n2y,n2z,n1x,n1y,n1z), lo), hi);
        float s = dot3_(u2x,u2y,u2z,n1x,n1y,n1z);
        float sg = (s > 0.0f) ? 1.0f : ((s < 0.0f) ? -1.0f : 0.0f);
        float Dang = fmul_(sg, acosf(cosD));

        float sA = sinf(A);
        a0 = cosf(A);
        a1 = fmul_(sA, cosf(Dang));
        a2 = fmul_(sA, sinf(Dang));

        float o1x=fsub_(u2x,u1x), o1y=fsub_(u2y,u1y), o1z=fsub_(u2z,u1z); norm3_(o1x,o1y,o1z);
        float cx,cy,cz; cross3_(o1x,o1y,o1z,n2x,n2y,n2z,cx,cy,cz);
        O0=o1x; O1=o1y; O2=o1z; O3v=n2x; O4=n2y; O5=n2z; O6=cx; O7=cy; O8=cz;
    }
    sOmRow[0]=O0; sOmRow[1]=O1; sOmRow[2]=O2; sOmRow[3]=O3v; sOmRow[4]=O4;
    sOmRow[5]=O5; sOmRow[6]=O6; sOmRow[7]=O7; sOmRow[8]=O8;
    outAD[id*3+0]=a0; outAD[id*3+1]=a1; outAD[id*3+2]=a2;
}

// ---- pre-pass: pack coords + squared norms ----
__global__ void pack_kernel(const float* __restrict__ X){
    int id = blockIdx.x*blockDim.x + threadIdx.x;
    if (id < BB*NN){
        float x = X[id*3+0], y = X[id*3+1], z = X[id*3+2];
        g_pts4[id] = make_float4(x, y, z, fmaf(z,z, fmaf(y,y, x*x)));
    }
}

// ============================================================================
// Fused kernel v13: v10 + higher occupancy (minblocks 5) + deeper unroll.
// ============================================================================
#define TPB 256
#define RB  8
#define CAP 224

__global__ __launch_bounds__(TPB, 5) void fused_kernel(
    const float* __restrict__ X, float* __restrict__ out)
{
    __shared__ __align__(16) u32 nib[NN];         // 16KB; reused by split-rank
    __shared__ u64   cand[RB][CAP];               // 14KB
    __shared__ float stD[RB][KK];
    __shared__ int   stI[RB][KK];
    __shared__ float sOm[RB][9];
    __shared__ float sThr[RB];
    __shared__ int   sTbin[RB];
    __shared__ float sfreq[8];
    __shared__ float smu[15];
    __shared__ int   scnt[RB];

    float* outP  = out + OFF_POS;
    float* outAD = out + OFF_AD;
    float* outO  = out + OFF_OF;
    float* outG  = out + OFF_GS;
    float* outD  = out + OFF_DN;
    float* outE  = out + OFF_EI;

    const int t = threadIdx.x, w = t >> 5, lane = t & 31;
    const int blk = blockIdx.x;
    const int b   = blk / (NN/RB);
    const int r0  = (blk % (NN/RB))*RB;
    const int bNN = b*NN;
    const float* Xb = X + b*NN*3;

    if (t < RB){
        node_work(X, outAD, bNN + r0 + t, sOm[t]);
        scnt[t] = 0;
    }
    if (t >= 32 && t < 64){
        int u = t - 32;
        if (u < 8){
            float argf = __fmul_rn((float)(2*u), -0.5756462732485115f);
            sfreq[u] = (float)exp((double)argf);
        }
        if (u < 15) smu[u] = (float)((double)u * (20.0/14.0));
    }

    // packed row registers: pair (q, q+4); nr biased by +1.01 (bin bias)
    u64 xr2[4], yr2[4], zr2[4], nr2[4];
    #pragma unroll
    for (int q = 0; q < 4; q++){
        float4 pa = g_pts4[bNN + r0 + q];
        float4 pb = g_pts4[bNN + r0 + q + 4];
        xr2[q] = pack2(pa.x, pb.x);
        yr2[q] = pack2(pa.y, pb.y);
        zr2[q] = pack2(pa.z, pb.z);
        nr2[q] = pack2(pa.w + 1.01f, pb.w + 1.01f);
    }
    const u64 M2 = pack2(-2.0f, -2.0f);
    __syncthreads();

    // ---- pass 1: packed fast-d2' bins, nibble cache ----
    // d2' = |i-j|^2 + 1.01 (approx) >= 1.007 -> bin = exponent - 127 in [0,15]
    #pragma unroll 4
    for (int m = 0; m < NN/TPB; m++){
        int j = m*TPB + t;
        float4 p = g_pts4[bNN + j];
        u64 xjj = pack2(p.x, p.x);
        u64 yjj = pack2(p.y, p.y);
        u64 zjj = pack2(p.z, p.z);
        u64 njj = pack2(p.w, p.w);
        u32 nibLo = 0u, nibHi = 0u;
        #pragma unroll
        for (int q = 3; q >= 0; q--){
            u64 s2 = fma2(xr2[q], xjj, fma2(yr2[q], yjj, mul2(zr2[q], zjj)));
            u64 d2 = fma2(M2, s2, add2(nr2[q], njj));
            u32 lo32 = (u32)d2;
            u32 hi32 = (u32)(d2 >> 32);
            nibLo = nibLo*16u + ((lo32 - 0x3F800000u) >> 23);
            nibHi = nibHi*16u + ((hi32 - 0x3F800000u) >> 23);
        }
        nib[j] = nibHi*65536u + nibLo;
    }
    __syncthreads();

    // ---- pass 1.5: warp w histograms row w from nibble cache (uint4) ----
    {
        u32 h0=0u, h1=0u, h2=0u, h3=0u;   // 16 bins x u8
        const int sh = w*4;
        const uint4* nib4 = (const uint4*)nib;
        #pragma unroll 2
        for (int u = 0; u < 32; u++){
            uint4 qv = nib4[u*32 + lane];
            u32 ws[4] = {qv.x, qv.y, qv.z, qv.w};
            #pragma unroll
            for (int e = 0; e < 4; e++){
                u32 bin = (ws[e] >> sh) & 15u;
                u32 add = 1u << ((bin & 3u) << 3);
                u32 sel = bin >> 2;
                if      (sel == 0u) h0 += add;
                else if (sel == 1u) h1 += add;
                else if (sel == 2u) h2 += add;
                else                h3 += add;
            }
        }
        u32 v[8];
        v[0]= h0      & 0x00FF00FFu; v[1]=(h0>>8) & 0x00FF00FFu;
        v[2]= h1      & 0x00FF00FFu; v[3]=(h1>>8) & 0x00FF00FFu;
        v[4]= h2      & 0x00FF00FFu; v[5]=(h2>>8) & 0x00FF00FFu;
        v[6]= h3      & 0x00FF00FFu; v[7]=(h3>>8) & 0x00FF00FFu;
        #pragma unroll
        for (int off = 16; off; off >>= 1){
            #pragma unroll
            for (int q = 0; q < 8; q++)
                v[q] += __shfl_xor_sync(0xffffffffu, v[q], off);
        }
        int cum = 0, T = 15;
        #pragma unroll
        for (int i = 0; i < 16; i++){
            u32 word = v[(i>>2)*2 + (i&1)];
            cum += (int)((word >> (((i>>1)&1)*16)) & 0xFFFFu);
            if (cum >= KK){ T = i; break; }
        }
        if (lane == 0){
            sTbin[w] = T;
            // keep: d2' < 2^(T+1) * (1 + 1/64); sliver covers fast-vs-exact eps
            sThr[w] = __uint_as_float(((u32)(128 + T) << 23) | 0x020000u);
        }
    }
    __syncthreads();

    // negated packed thresholds per row pair
    u64 nThr2[4];
    #pragma unroll
    for (int q = 0; q < 4; q++)
        nThr2[q] = pack2(-sThr[q], -sThr[q+4]);

    // ---- pass 2: packed recompute, sign-mask keep test ----
    #pragma unroll 4
    for (int m = 0; m < NN/TPB; m++){
        int j = m*TPB + t;
        float4 p = g_pts4[bNN + j];
        u64 xjj = pack2(p.x, p.x);
        u64 yjj = pack2(p.y, p.y);
        u64 zjj = pack2(p.z, p.z);
        u64 njj = pack2(p.w, p.w);
        #pragma unroll
        for (int q = 0; q < 4; q++){
            u64 s2 = fma2(xr2[q], xjj, fma2(yr2[q], yjj, mul2(zr2[q], zjj)));
            u64 d2 = fma2(M2, s2, add2(nr2[q], njj));
            u64 df = add2(d2, nThr2[q]);          // d2' - thr, per half
            if (df & 0x8000000080000000ull){
                if ((u32)(df >> 31) & 1u){        // low half negative -> row q
                    int pos = atomicAdd(&scnt[q], 1);
                    if (pos < CAP) cand[q][pos] = (u64)j;
                }
                if (df >> 63){                    // high half -> row q+4
                    int pos = atomicAdd(&scnt[q+4], 1);
                    if (pos < CAP) cand[q+4][pos] = (u64)j;
                }
            }
        }
    }
    __syncthreads();

    // ---- extraction: exact (D, j) keys + split-rank (warp w = row w) ----
    {
        const int row = r0 + w;
        const int c = min(scnt[w], CAP);
        const int base = (bNN + row)*KK;
        const float xi = Xb[row*3+0], yi = Xb[row*3+1], zi = Xb[row*3+2];

        for (int idx = lane; idx < c; idx += 32){
            u32 j = (u32)cand[w][idx];
            float xj = __ldg(&Xb[j*3+0]);
            float yj = __ldg(&Xb[j*3+1]);
            float zj = __ldg(&Xb[j*3+2]);
            float d2 = d2_exact(xi,yi,zi,xj,yj,zj);
            float D  = __fsqrt_rn(fadd_(d2, 1e-6f));
            cand[w][idx] = ((u64)__float_as_uint(D) << 32) | j;
        }
        __syncwarp();

        // pivot: lower edge of bin T mapped to exact-D domain (any pivot is valid)
        const int T = sTbin[w];
        float pd2 = fmaxf(__uint_as_float((u32)(127 + T) << 23) - 1.01f, 0.0f);
        float pD  = __fsqrt_rn(fadd_(pd2, 1e-6f));
        const u64 Kp = ((u64)__float_as_uint(pD)) << 32;
        u64* sp = ((u64*)nib) + w*CAP;

        const int iters = (c + 31) >> 5;
        int totA = 0;
        for (int u = 0; u < iters; u++){
            int idx = u*32 + lane;
            bool A = (idx < c) && (cand[w][idx] < Kp);
            totA += __popc(__ballot_sync(0xffffffffu, A));
        }
        int runA = 0, runB = 0;
        for (int u = 0; u < iters; u++){
            int idx = u*32 + lane;
            bool valid = idx < c;
            u64 k = valid ? cand[w][idx] : 0xFFFFFFFFFFFFFFFFull;
            bool A = valid && (k < Kp);
            u32 mA = __ballot_sync(0xffffffffu, A);
            u32 mB = __ballot_sync(0xffffffffu, valid && !A);
            if (valid){
                u32 below = (1u << lane) - 1u;
                int pos = A ? (runA + __popc(mA & below))
                            : (totA + runB + __popc(mB & below));
                sp[pos] = k;
            }
            runA += __popc(mA);
            runB += __popc(mB);
        }
        __syncwarp();

        for (int idx = lane; idx < c; idx += 32){
            u64 k = sp[idx];
            bool isA = idx < totA;
            int s0 = isA ? 0 : totA;
            int s1 = isA ? totA : c;
            int rank = isA ? 0 : totA;
            for (int cc = s0; cc < s1; cc++)
                rank += (sp[cc] < k) ? 1 : 0;
            if (rank < KK){
                u32 jj = (u32)(k & 0xFFFFFFFFull);
                float D = __uint_as_float((u32)(k >> 32));
                outD[base + rank] = D;
                outE[base + rank] = (float)jj;
                stD[w][rank] = D;
                stI[w][rank] = (int)jj;
            }
        }
    }
    __syncthreads();

    // ---- edge phase A: positional encodings (8 x 30 x 16, coalesced) ----
    for (int id = t; id < RB*KK*16; id += TPB){
        int r = id / (KK*16);
        int q = id - r*(KK*16);
        int k = q >> 4, m = q & 15;
        int i = r0 + r;
        int j = stI[r][k];
        float d = fsub_((float)j, (float)i);
        float ang = fmul_(d, sfreq[m & 7]);
        float rr = red2pi_(ang);
        outP[(size_t)(bNN + i)*(KK*16) + q] = (m < 8) ? __cosf(rr) : __sinf(rr);
    }

    // ---- edge phase B: gaussian smearing (8 x 30 x 15, coalesced) ----
    for (int id = t; id < RB*KK*15; id += TPB){
        int r = id / (KK*15);
        int q = id - r*(KK*15);
        int k = q / 15, m = q - k*15;
        float D  = stD[r][k];
        float tt = fsub_(D, smu[m]) * 0.74999998f;
        outG[(size_t)(bNN + r0 + r)*(KK*15) + q] = __expf(-tt*tt);
    }

    // ---- edge phase C: dU via rsqrt normalize (8 x 30 edges) ----
    if (t < RB*KK){
        int r = t / KK, k = t - r*KK;
        int i = r0 + r;
        int j = stI[r][k];
        float dx = fsub_(Xb[j*3+0], Xb[i*3+0]);
        float dy = fsub_(Xb[j*3+1], Xb[i*3+1]);
        float dz = fsub_(Xb[j*3+2], Xb[i*3+2]);
        const float* Om = sOm[r];
        float v0 = dot3_(Om[0],Om[1],Om[2], dx,dy,dz);
        float v1 = dot3_(Om[3],Om[4],Om[5], dx,dy,dz);
        float v2 = dot3_(Om[6],Om[7],Om[8], dx,dy,dz);
        float s  = dot3_(v0,v1,v2,v0,v1,v2);
        float rn = rsqrtf(fmaxf(s, 1e-24f));
        size_t o = (size_t)((bNN + i)*KK + k)*3;
        outO[o+0] = v0*rn;
        outO[o+1] = v1*rn;
        outO[o+2] = v2*rn;
    }
}

// ============================================================================
extern "C" void kernel_launch(void* const* d_in, const int* in_sizes, int n_in,
                              void* d_out, int out_size)
{
    const float* X = (const float*)d_in[0];
    float* out = (float*)d_out;
    pack_kernel<<<(BB*NN + 255)/256, 256>>>(X);
    fused_kernel<<<BB*NN/RB, TPB>>>(X, out);
}

// round 14
// speedup vs baseline: 11.3563x; 1.0118x over previous
#include <cuda_runtime.h>
#include <math.h>

#define BB 2
#define NN 4096
#define KK 30

#define SZ_POS (BB*NN*KK*16)
#define SZ_AD  (BB*NN*3)
#define SZ_OF  (BB*NN*KK*3)
#define SZ_GS  (BB*NN*KK*15)
#define SZ_DN  (BB*NN*KK)

#define OFF_POS 0
#define OFF_AD  (OFF_POS + SZ_POS)
#define OFF_OF  (OFF_AD  + SZ_AD)
#define OFF_GS  (OFF_OF  + SZ_OF)
#define OFF_DN  (OFF_GS  + SZ_GS)
#define OFF_EI  (OFF_DN  + SZ_DN)

typedef unsigned long long u64;
typedef unsigned int       u32;

// ---- scratch ----
static __device__ float4 g_pts4[BB*NN];   // (x, y, z, |p|^2)

// ---- packed f32x2 helpers (sm_103a FFMA2 path, PTX-only) ----
__device__ __forceinline__ u64 pack2(float lo, float hi){
    u64 d; asm("mov.b64 %0, {%1, %2};" : "=l"(d) : "f"(lo), "f"(hi)); return d;
}
__device__ __forceinline__ u64 fma2(u64 a, u64 b, u64 c){
    u64 d; asm("fma.rn.f32x2 %0, %1, %2, %3;" : "=l"(d) : "l"(a), "l"(b), "l"(c)); return d;
}
__device__ __forceinline__ u64 mul2(u64 a, u64 b){
    u64 d; asm("mul.rn.f32x2 %0, %1, %2;" : "=l"(d) : "l"(a), "l"(b)); return d;
}
__device__ __forceinline__ u64 add2(u64 a, u64 b){
    u64 d; asm("add.rn.f32x2 %0, %1, %2;" : "=l"(d) : "l"(a), "l"(b)); return d;
}

// ---- exact-rounding helpers (OUTPUT values / selection keys) ----
__device__ __forceinline__ float fadd_(float a, float b){ return __fadd_rn(a,b); }
__device__ __forceinline__ float fsub_(float a, float b){ return __fsub_rn(a,b); }
__device__ __forceinline__ float fmul_(float a, float b){ return __fmul_rn(a,b); }
__device__ __forceinline__ float dot3_(float ax,float ay,float az,
                                       float bx,float by,float bz){
    return fadd_(fadd_(fmul_(ax,bx), fmul_(ay,by)), fmul_(az,bz));
}
__device__ __forceinline__ void norm3_(float &x, float &y, float &z){
    float n = __fsqrt_rn(dot3_(x,y,z,x,y,z));
    n = fmaxf(n, 1e-12f);
    x = __fdiv_rn(x,n); y = __fdiv_rn(y,n); z = __fdiv_rn(z,n);
}
__device__ __forceinline__ void cross3_(float ax,float ay,float az,
                                        float bx,float by,float bz,
                                        float &cx,float &cy,float &cz){
    cx = fsub_(fmul_(ay,bz), fmul_(az,by));
    cy = fsub_(fmul_(az,bx), fmul_(ax,bz));
    cz = fsub_(fmul_(ax,by), fmul_(ay,bx));
}
__device__ __forceinline__ float d2_exact(float xi,float yi,float zi,
                                          float xj,float yj,float zj){
    float dx = fsub_(xj,xi), dy = fsub_(yj,yi), dz = fsub_(zj,zi);
    return fadd_(fadd_(fmul_(dx,dx), fmul_(dy,dy)), fmul_(dz,dz));
}

// ---- FP32 Cody-Waite 2pi reduction ----
#define INV_2PI  0.15915494309189535f
#define PI2_C1   6.2831855f
#define PI2_C2  -1.7484555e-07f
#define PI2_C3  -5.4469782e-15f
__device__ __forceinline__ float red2pi_(float ang){
    float k = rintf(ang * INV_2PI);
    float r = fmaf(-k, PI2_C1, ang);
    r = fmaf(-k, PI2_C2, r);
    r = fmaf(-k, PI2_C3, r);
    return r;
}

// ---- per-node orientation matrix + AD ----
__device__ void node_work(const float* __restrict__ X, float* __restrict__ outAD,
                          int id, float* __restrict__ sOmRow){
    int b = id / NN, n = id % NN;

    float O0=0,O1=0,O2=0,O3v=0,O4=0,O5=0,O6=0,O7=0,O8=0;
    float a0=0,a1=0,a2=0;

    if (n >= 1 && n <= NN-3){
        const float* Xb = X + b*NN*3;
        float p0x=Xb[(n-1)*3+0], p0y=Xb[(n-1)*3+1], p0z=Xb[(n-1)*3+2];
        float p1x=Xb[(n  )*3+0], p1y=Xb[(n  )*3+1], p1z=Xb[(n  )*3+2];
        float p2x=Xb[(n+1)*3+0], p2y=Xb[(n+1)*3+1], p2z=Xb[(n+1)*3+2];
        float p3x=Xb[(n+2)*3+0], p3y=Xb[(n+2)*3+1], p3z=Xb[(n+2)*3+2];

        float u2x=fsub_(p1x,p0x), u2y=fsub_(p1y,p0y), u2z=fsub_(p1z,p0z); norm3_(u2x,u2y,u2z);
        float u1x=fsub_(p2x,p1x), u1y=fsub_(p2y,p1y), u1z=fsub_(p2z,p1z); norm3_(u1x,u1y,u1z);
        float u0x=fsub_(p3x,p2x), u0y=fsub_(p3y,p2y), u0z=fsub_(p3z,p2z); norm3_(u0x,u0y,u0z);

        float n2x,n2y,n2z; cross3_(u2x,u2y,u2z,u1x,u1y,u1z,n2x,n2y,n2z); norm3_(n2x,n2y,n2z);
        float n1x,n1y,n1z; cross3_(u1x,u1y,u1z,u0x,u0y,u0z,n1x,n1y,n1z); norm3_(n1x,n1y,n1z);

        const float lo = (float)(-1.0 + 1e-6);
        const float hi = (float)( 1.0 - 1e-6);
        float cosA = fminf(fmaxf(-dot3_(u1x,u1y,u1z,u0x,u0y,u0z), lo), hi);
        float A = acosf(cosA);
        float cosD = fminf(fmaxf(dot3_(n2x,n2y,n2z,n1x,n1y,n1z), lo), hi);
        float s = dot3_(u2x,u2y,u2z,n1x,n1y,n1z);
        float sg = (s > 0.0f) ? 1.0f : ((s < 0.0f) ? -1.0f : 0.0f);
        float Dang = fmul_(sg, acosf(cosD));

        float sA = sinf(A);
        a0 = cosf(A);
        a1 = fmul_(sA, cosf(Dang));
        a2 = fmul_(sA, sinf(Dang));

        float o1x=fsub_(u2x,u1x), o1y=fsub_(u2y,u1y), o1z=fsub_(u2z,u1z); norm3_(o1x,o1y,o1z);
        float cx,cy,cz; cross3_(o1x,o1y,o1z,n2x,n2y,n2z,cx,cy,cz);
        O0=o1x; O1=o1y; O2=o1z; O3v=n2x; O4=n2y; O5=n2z; O6=cx; O7=cy; O8=cz;
    }
    sOmRow[0]=O0; sOmRow[1]=O1; sOmRow[2]=O2; sOmRow[3]=O3v; sOmRow[4]=O4;
    sOmRow[5]=O5; sOmRow[6]=O6; sOmRow[7]=O7; sOmRow[8]=O8;
    outAD[id*3+0]=a0; outAD[id*3+1]=a1; outAD[id*3+2]=a2;
}

// ---- pre-pass: pack coords + squared norms ----
__global__ void pack_kernel(const float* __restrict__ X){
    int id = blockIdx.x*blockDim.x + threadIdx.x;
    if (id < BB*NN){
        float x = X[id*3+0], y = X[id*3+1], z = X[id*3+2];
        g_pts4[id] = make_float4(x, y, z, fmaf(z,z, fmaf(y,y, x*x)));
    }
}

// ============================================================================
// Fused kernel v14: v10 + SWAR nibble pre-filter in pass 2.
// ============================================================================
#define TPB 256
#define RB  8
#define CAP 224

__global__ __launch_bounds__(TPB) void fused_kernel(
    const float* __restrict__ X, float* __restrict__ out)
{
    __shared__ __align__(16) u32 nib[NN];         // 16KB; reused by split-rank
    __shared__ u64   cand[RB][CAP];               // 14KB
    __shared__ float stD[RB][KK];
    __shared__ int   stI[RB][KK];
    __shared__ float sOm[RB][9];
    __shared__ float sThr[RB];
    __shared__ int   sTbin[RB];
    __shared__ float sfreq[8];
    __shared__ float smu[15];
    __shared__ int   scnt[RB];

    float* outP  = out + OFF_POS;
    float* outAD = out + OFF_AD;
    float* outO  = out + OFF_OF;
    float* outG  = out + OFF_GS;
    float* outD  = out + OFF_DN;
    float* outE  = out + OFF_EI;

    const int t = threadIdx.x, w = t >> 5, lane = t & 31;
    const int blk = blockIdx.x;
    const int b   = blk / (NN/RB);
    const int r0  = (blk % (NN/RB))*RB;
    const int bNN = b*NN;
    const float* Xb = X + b*NN*3;

    if (t < RB){
        node_work(X, outAD, bNN + r0 + t, sOm[t]);
        scnt[t] = 0;
    }
    if (t >= 32 && t < 64){
        int u = t - 32;
        if (u < 8){
            float argf = __fmul_rn((float)(2*u), -0.5756462732485115f);
            sfreq[u] = (float)exp((double)argf);
        }
        if (u < 15) smu[u] = (float)((double)u * (20.0/14.0));
    }

    // packed row registers: pair (q, q+4); nr biased by +1.01 (bin bias)
    u64 xr2[4], yr2[4], zr2[4], nr2[4];
    #pragma unroll
    for (int q = 0; q < 4; q++){
        float4 pa = g_pts4[bNN + r0 + q];
        float4 pb = g_pts4[bNN + r0 + q + 4];
        xr2[q] = pack2(pa.x, pb.x);
        yr2[q] = pack2(pa.y, pb.y);
        zr2[q] = pack2(pa.z, pb.z);
        nr2[q] = pack2(pa.w + 1.01f, pb.w + 1.01f);
    }
    const u64 M2 = pack2(-2.0f, -2.0f);
    __syncthreads();

    // ---- pass 1: packed fast-d2' bins, nibble cache ----
    // d2' = |i-j|^2 + 1.01 (approx) >= 1.007 -> bin = exponent - 127 in [0,15]
    #pragma unroll 2
    for (int m = 0; m < NN/TPB; m++){
        int j = m*TPB + t;
        float4 p = g_pts4[bNN + j];
        u64 xjj = pack2(p.x, p.x);
        u64 yjj = pack2(p.y, p.y);
        u64 zjj = pack2(p.z, p.z);
        u64 njj = pack2(p.w, p.w);
        u32 nibLo = 0u, nibHi = 0u;
        #pragma unroll
        for (int q = 3; q >= 0; q--){
            u64 s2 = fma2(xr2[q], xjj, fma2(yr2[q], yjj, mul2(zr2[q], zjj)));
            u64 d2 = fma2(M2, s2, add2(nr2[q], njj));
            u32 lo32 = (u32)d2;
            u32 hi32 = (u32)(d2 >> 32);
            nibLo = nibLo*16u + ((lo32 - 0x3F800000u) >> 23);
            nibHi = nibHi*16u + ((hi32 - 0x3F800000u) >> 23);
        }
        nib[j] = nibHi*65536u + nibLo;
    }
    __syncthreads();

    // ---- pass 1.5: warp w histograms row w from nibble cache (uint4) ----
    {
        u32 h0=0u, h1=0u, h2=0u, h3=0u;   // 16 bins x u8
        const int sh = w*4;
        const uint4* nib4 = (const uint4*)nib;
        #pragma unroll 2
        for (int u = 0; u < 32; u++){
            uint4 qv = nib4[u*32 + lane];
            u32 ws[4] = {qv.x, qv.y, qv.z, qv.w};
            #pragma unroll
            for (int e = 0; e < 4; e++){
                u32 bin = (ws[e] >> sh) & 15u;
                u32 add = 1u << ((bin & 3u) << 3);
                u32 sel = bin >> 2;
                if      (sel == 0u) h0 += add;
                else if (sel == 1u) h1 += add;
                else if (sel == 2u) h2 += add;
                else                h3 += add;
            }
        }
        u32 v[8];
        v[0]= h0      & 0x00FF00FFu; v[1]=(h0>>8) & 0x00FF00FFu;
        v[2]= h1      & 0x00FF00FFu; v[3]=(h1>>8) & 0x00FF00FFu;
        v[4]= h2      & 0x00FF00FFu; v[5]=(h2>>8) & 0x00FF00FFu;
        v[6]= h3      & 0x00FF00FFu; v[7]=(h3>>8) & 0x00FF00FFu;
        #pragma unroll
        for (int off = 16; off; off >>= 1){
            #pragma unroll
            for (int q = 0; q < 8; q++)
                v[q] += __shfl_xor_sync(0xffffffffu, v[q], off);
        }
        int cum = 0, T = 15;
        #pragma unroll
        for (int i = 0; i < 16; i++){
            u32 word = v[(i>>2)*2 + (i&1)];
            cum += (int)((word >> (((i>>1)&1)*16)) & 0xFFFFu);
            if (cum >= KK){ T = i; break; }
        }
        if (lane == 0){
            sTbin[w] = T;
            // keep: d2' < 2^(T+1) * (1 + 1/64); sliver covers fast-vs-exact eps
            sThr[w] = __uint_as_float(((u32)(128 + T) << 23) | 0x020000u);
        }
    }
    __syncthreads();

    // negated packed thresholds per row pair + SWAR nibble byte-thresholds
    u64 nThr2[4];
    #pragma unroll
    for (int q = 0; q < 4; q++)
        nThr2[q] = pack2(-sThr[q], -sThr[q+4]);
    // even nibbles (rows 0,2,4,6) / odd nibbles (rows 1,3,5,7), margin +1 bin
    u32 Te = 0u, To = 0u;
    #pragma unroll
    for (int r = 0; r < 4; r++){
        Te |= (u32)min(sTbin[2*r]   + 1, 15) << (r*8);
        To |= (u32)min(sTbin[2*r+1] + 1, 15) << (r*8);
    }

    // ---- pass 2: SWAR nibble pre-filter, packed float verify on hit ----
    #pragma unroll 2
    for (int m = 0; m < NN/TPB; m++){
        int j = m*TPB + t;
        u32 nb = nib[j];
        u32 hit = __vcmpleu4( nb        & 0x0F0F0F0Fu, Te)
                | __vcmpleu4((nb >> 4)  & 0x0F0F0F0Fu, To);
        if (hit){
            float4 p = g_pts4[bNN + j];
            u64 xjj = pack2(p.x, p.x);
            u64 yjj = pack2(p.y, p.y);
            u64 zjj = pack2(p.z, p.z);
            u64 njj = pack2(p.w, p.w);
            #pragma unroll
            for (int q = 0; q < 4; q++){
                u64 s2 = fma2(xr2[q], xjj, fma2(yr2[q], yjj, mul2(zr2[q], zjj)));
                u64 d2 = fma2(M2, s2, add2(nr2[q], njj));
                u64 df = add2(d2, nThr2[q]);          // d2' - thr, per half
                if (df & 0x8000000080000000ull){
                    if ((u32)(df >> 31) & 1u){        // low half -> row q
                        int pos = atomicAdd(&scnt[q], 1);
                        if (pos < CAP) cand[q][pos] = (u64)j;
                    }
                    if (df >> 63){                    // high half -> row q+4
                        int pos = atomicAdd(&scnt[q+4], 1);
                        if (pos < CAP) cand[q+4][pos] = (u64)j;
                    }
                }
            }
        }
    }
    __syncthreads();

    // ---- extraction: exact (D, j) keys + split-rank (warp w = row w) ----
    {
        const int row = r0 + w;
        const int c = min(scnt[w], CAP);
        const int base = (bNN + row)*KK;
        const float xi = Xb[row*3+0], yi = Xb[row*3+1], zi = Xb[row*3+2];

        for (int idx = lane; idx < c; idx += 32){
            u32 j = (u32)cand[w][idx];
            float4 pj = g_pts4[bNN + j];
            float d2 = d2_exact(xi,yi,zi, pj.x,pj.y,pj.z);
            float D  = __fsqrt_rn(fadd_(d2, 1e-6f));
            cand[w][idx] = ((u64)__float_as_uint(D) << 32) | j;
        }
        __syncwarp();

        // pivot: lower edge of bin T mapped to exact-D domain (any pivot is valid)
        const int T = sTbin[w];
        float pd2 = fmaxf(__uint_as_float((u32)(127 + T) << 23) - 1.01f, 0.0f);
        float pD  = __fsqrt_rn(fadd_(pd2, 1e-6f));
        const u64 Kp = ((u64)__float_as_uint(pD)) << 32;
        u64* sp = ((u64*)nib) + w*CAP;

        const int iters = (c + 31) >> 5;
        int totA = 0;
        for (int u = 0; u < iters; u++){
            int idx = u*32 + lane;
            bool A = (idx < c) && (cand[w][idx] < Kp);
            totA += __popc(__ballot_sync(0xffffffffu, A));
        }
        int runA = 0, runB = 0;
        for (int u = 0; u < iters; u++){
            int idx = u*32 + lane;
            bool valid = idx < c;
            u64 k = valid ? cand[w][idx] : 0xFFFFFFFFFFFFFFFFull;
            bool A = valid && (k < Kp);
            u32 mA = __ballot_sync(0xffffffffu, A);
            u32 mB = __ballot_sync(0xffffffffu, valid && !A);
            if (valid){
                u32 below = (1u << lane) - 1u;
                int pos = A ? (runA + __popc(mA & below))
                            : (totA + runB + __popc(mB & below));
                sp[pos] = k;
            }
            runA += __popc(mA);
            runB += __popc(mB);
        }
        __syncwarp();

        for (int idx = lane; idx < c; idx += 32){
            u64 k = sp[idx];
            bool isA = idx < totA;
            int s0 = isA ? 0 : totA;
            int s1 = isA ? totA : c;
            int rank = isA ? 0 : totA;
            for (int cc = s0; cc < s1; cc++)
                rank += (sp[cc] < k) ? 1 : 0;
            if (rank < KK){
                u32 jj = (u32)(k & 0xFFFFFFFFull);
                float D = __uint_as_float((u32)(k >> 32));
                outD[base + rank] = D;
                outE[base + rank] = (float)jj;
                stD[w][rank] = D;
                stI[w][rank] = (int)jj;
            }
        }
    }
    __syncthreads();

    // ---- edge phase A: positional encodings (8 x 30 x 16, coalesced) ----
    for (int id = t; id < RB*KK*16; id += TPB){
        int r = id / (KK*16);
        int q = id - r*(KK*16);
        int k = q >> 4, m = q & 15;
        int i = r0 + r;
        int j = stI[r][k];
        float d = fsub_((float)j, (float)i);
        float ang = fmul_(d, sfreq[m & 7]);
        float rr = red2pi_(ang);
        outP[(size_t)(bNN + i)*(KK*16) + q] = (m < 8) ? __cosf(rr) : __sinf(rr);
    }

    // ---- edge phase B: gaussian smearing (8 x 30 x 15, coalesced) ----
    for (int id = t; id < RB*KK*15; id += TPB){
        int r = id / (KK*15);
        int q = id - r*(KK*15);
        int k = q / 15, m = q - k*15;
        float D  = stD[r][k];
        float tt = fsub_(D, smu[m]) * 0.74999998f;
        outG[(size_t)(bNN + r0 + r)*(KK*15) + q] = __expf(-tt*tt);
    }

    // ---- edge phase C: dU via rsqrt normalize (8 x 30 edges) ----
    if (t < RB*KK){
        int r = t / KK, k = t - r*KK;
        int i = r0 + r;
        int j = stI[r][k];
        float dx = fsub_(Xb[j*3+0], Xb[i*3+0]);
        float dy = fsub_(Xb[j*3+1], Xb[i*3+1]);
        float dz = fsub_(Xb[j*3+2], Xb[i*3+2]);
        const float* Om = sOm[r];
        float v0 = dot3_(Om[0],Om[1],Om[2], dx,dy,dz);
        float v1 = dot3_(Om[3],Om[4],Om[5], dx,dy,dz);
        float v2 = dot3_(Om[6],Om[7],Om[8], dx,dy,dz);
        float s  = dot3_(v0,v1,v2,v0,v1,v2);
        float rn = rsqrtf(fmaxf(s, 1e-24f));
        size_t o = (size_t)((bNN + i)*KK + k)*3;
        outO[o+0] = v0*rn;
        outO[o+1] = v1*rn;
        outO[o+2] = v2*rn;
    }
}

// ============================================================================
extern "C" void kernel_launch(void* const* d_in, const int* in_sizes, int n_in,
                              void* d_out, int out_size)
{
    const float* X = (const float*)d_in[0];
    float* out = (float*)d_out;
    pack_kernel<<<(BB*NN + 255)/256, 256>>>(X);
    fused_kernel<<<BB*NN/RB, TPB>>>(X, out);
}